// round 1
// baseline (speedup 1.0000x reference)
#include <cuda_runtime.h>
#include <cstdint>

// Problem constants
#define BB 16384
#define KK 64
#define MM 6
#define NA 16

// Precomputed rotation table: R[action][k][6][6]  (16*64*36 floats = 144 KB)
// Aligned for float4 access.
__device__ __align__(16) float d_R[NA * KK * MM * MM];

// ---------------------------------------------------------------------------
// Kernel 1: compute the 1024 distinct 6x6 matrix exponentials.
//   A = a * (L - L^T)  (skew),  E = expm(A) via scaling-and-squaring +
//   order-12 Taylor (Horner).  One thread per (action, k).
// ---------------------------------------------------------------------------
__global__ void expm_kernel(const float* __restrict__ act_params,
                            const float* __restrict__ basis) {
    int idx = blockIdx.x * blockDim.x + threadIdx.x;
    if (idx >= NA * KK) return;
    int action = idx / KK;
    int k = idx - action * KK;

    float a = act_params[action * KK + k];
    const float* L = basis + k * 36;

    float A[36];
#pragma unroll
    for (int i = 0; i < 6; i++)
#pragma unroll
        for (int j = 0; j < 6; j++)
            A[i * 6 + j] = a * (L[i * 6 + j] - L[j * 6 + i]);

    // infinity norm
    float nrm = 0.f;
#pragma unroll
    for (int i = 0; i < 6; i++) {
        float rs = 0.f;
#pragma unroll
        for (int j = 0; j < 6; j++) rs += fabsf(A[i * 6 + j]);
        nrm = fmaxf(nrm, rs);
    }

    // scaling: bring norm below 0.5
    int s = 0;
    while (nrm > 0.5f && s < 40) { nrm *= 0.5f; s++; }
    float sc = ldexpf(1.0f, -s);
#pragma unroll
    for (int i = 0; i < 36; i++) A[i] *= sc;

    // Taylor via Horner:  T = I;  for p=12..1:  T = I + (A*T)/p
    float T[36];
#pragma unroll
    for (int i = 0; i < 36; i++) T[i] = 0.f;
#pragma unroll
    for (int i = 0; i < 6; i++) T[i * 6 + i] = 1.f;

    for (int p = 12; p >= 1; --p) {
        float tmp[36];
        float inv = 1.0f / (float)p;
#pragma unroll
        for (int i = 0; i < 6; i++)
#pragma unroll
            for (int j = 0; j < 6; j++) {
                float acc = 0.f;
#pragma unroll
                for (int m = 0; m < 6; m++)
                    acc = fmaf(A[i * 6 + m], T[m * 6 + j], acc);
                tmp[i * 6 + j] = acc * inv + ((i == j) ? 1.f : 0.f);
            }
#pragma unroll
        for (int i = 0; i < 36; i++) T[i] = tmp[i];
    }

    // squaring phase
    for (int q = 0; q < s; q++) {
        float tmp[36];
#pragma unroll
        for (int i = 0; i < 6; i++)
#pragma unroll
            for (int j = 0; j < 6; j++) {
                float acc = 0.f;
#pragma unroll
                for (int m = 0; m < 6; m++)
                    acc = fmaf(T[i * 6 + m], T[m * 6 + j], acc);
                tmp[i * 6 + j] = acc;
            }
#pragma unroll
        for (int i = 0; i < 36; i++) T[i] = tmp[i];
    }

    float* outp = d_R + idx * 36;
#pragma unroll
    for (int i = 0; i < 36; i++) outp[i] = T[i];
}

// ---------------------------------------------------------------------------
// Kernel 2: streaming apply.  One thread per (b,k) 6x6 block.
//   out[b,k] = R[act[b], k] @ gf[b,k]
// Fully vectorized float4 loads/stores; row-pair inner loop keeps register
// pressure low enough for >=2 CTAs/SM.
// ---------------------------------------------------------------------------
__global__ void __launch_bounds__(256, 2) apply_kernel(
    const float* __restrict__ gf,
    const int* __restrict__ act,
    float* __restrict__ out) {
    unsigned idx = blockIdx.x * 256u + threadIdx.x;   // 0 .. B*K-1
    unsigned b = idx >> 6;
    unsigned k = idx & 63u;

    int a = __ldg(act + b);

    size_t off = (size_t)idx * 36;
    const float4* g4 = reinterpret_cast<const float4*>(gf + off);

    float G[36];
#pragma unroll
    for (int q = 0; q < 9; q++) {
        float4 v = __ldg(g4 + q);
        G[4 * q + 0] = v.x; G[4 * q + 1] = v.y;
        G[4 * q + 2] = v.z; G[4 * q + 3] = v.w;
    }

    const float4* R4 = reinterpret_cast<const float4*>(
        d_R + ((unsigned)a * (unsigned)KK + k) * 36u);
    float4* o4 = reinterpret_cast<float4*>(out + off);

#pragma unroll
    for (int rp = 0; rp < 3; rp++) {
        // two rows of R (12 floats, 16B-aligned: rp*48 bytes)
        float r[12];
#pragma unroll
        for (int q = 0; q < 3; q++) {
            float4 v = __ldg(R4 + rp * 3 + q);
            r[4 * q + 0] = v.x; r[4 * q + 1] = v.y;
            r[4 * q + 2] = v.z; r[4 * q + 3] = v.w;
        }
        // two rows of P
        float p[12];
#pragma unroll
        for (int l = 0; l < 6; l++) {
            float acc0 = 0.f, acc1 = 0.f;
#pragma unroll
            for (int j = 0; j < 6; j++) {
                acc0 = fmaf(r[j],     G[j * 6 + l], acc0);
                acc1 = fmaf(r[6 + j], G[j * 6 + l], acc1);
            }
            p[l] = acc0; p[6 + l] = acc1;
        }
#pragma unroll
        for (int q = 0; q < 3; q++) {
            float4 v;
            v.x = p[4 * q + 0]; v.y = p[4 * q + 1];
            v.z = p[4 * q + 2]; v.w = p[4 * q + 3];
            o4[rp * 3 + q] = v;
        }
    }
}

// ---------------------------------------------------------------------------
// Launch.  Inputs (metadata order): group_feats f32 [B, K*36], act i32 [B],
// act_params f32 [16, K], lie_alg_basis f32 [K, 6, 6].  Output f32 [B, K*36].
// ---------------------------------------------------------------------------
extern "C" void kernel_launch(void* const* d_in, const int* in_sizes, int n_in,
                              void* d_out, int out_size) {
    const float* gf         = (const float*)d_in[0];
    const int*   act        = (const int*)d_in[1];
    const float* act_params = (const float*)d_in[2];
    const float* basis      = (const float*)d_in[3];
    float* out = (float*)d_out;

    expm_kernel<<<(NA * KK + 255) / 256, 256>>>(act_params, basis);
    apply_kernel<<<(BB * KK) / 256, 256>>>(gf, act, out);
}

// round 3
// speedup vs baseline: 1.1620x; 1.1620x over previous
#include <cuda_runtime.h>
#include <cstdint>

#define BB 16384
#define KK 64
#define NA 16

// Precomputed rotation table: R[action][k][6][6]  (144 KB), float4-aligned.
__device__ __align__(16) float d_R[NA * KK * 36];

// ---------------------------------------------------------------------------
// Kernel 1: the 1024 distinct 6x6 expm's. One thread per (action,k).
// Launched <<<32,32>>> so 32 SMs run one warp each (FMA-issue bound, ~2.5us).
// ---------------------------------------------------------------------------
__global__ void expm_kernel(const float* __restrict__ act_params,
                            const float* __restrict__ basis) {
    int idx = blockIdx.x * blockDim.x + threadIdx.x;
    if (idx >= NA * KK) return;
    int action = idx >> 6;
    int k = idx & 63;

    float a = act_params[action * KK + k];
    const float* L = basis + k * 36;

    float A[36];
#pragma unroll
    for (int i = 0; i < 6; i++)
#pragma unroll
        for (int j = 0; j < 6; j++)
            A[i * 6 + j] = a * (L[i * 6 + j] - L[j * 6 + i]);

    // infinity norm
    float nrm = 0.f;
#pragma unroll
    for (int i = 0; i < 6; i++) {
        float rs = 0.f;
#pragma unroll
        for (int j = 0; j < 6; j++) rs += fabsf(A[i * 6 + j]);
        nrm = fmaxf(nrm, rs);
    }

    // scaling: bring norm below 0.5
    int s = 0;
    while (nrm > 0.5f && s < 40) { nrm *= 0.5f; s++; }
    float sc = ldexpf(1.0f, -s);
#pragma unroll
    for (int i = 0; i < 36; i++) A[i] *= sc;

    // Taylor (order 10) via Horner: T = I; for p=10..1: T = I + (A*T)/p
    float T[36];
#pragma unroll
    for (int i = 0; i < 36; i++) T[i] = 0.f;
#pragma unroll
    for (int i = 0; i < 6; i++) T[i * 6 + i] = 1.f;

    for (int p = 10; p >= 1; --p) {
        float tmp[36];
        float inv = 1.0f / (float)p;
#pragma unroll
        for (int i = 0; i < 6; i++)
#pragma unroll
            for (int j = 0; j < 6; j++) {
                float acc = 0.f;
#pragma unroll
                for (int m = 0; m < 6; m++)
                    acc = fmaf(A[i * 6 + m], T[m * 6 + j], acc);
                tmp[i * 6 + j] = acc * inv + ((i == j) ? 1.f : 0.f);
            }
#pragma unroll
        for (int i = 0; i < 36; i++) T[i] = tmp[i];
    }

    // squaring phase
    for (int q = 0; q < s; q++) {
        float tmp[36];
#pragma unroll
        for (int i = 0; i < 6; i++)
#pragma unroll
            for (int j = 0; j < 6; j++) {
                float acc = 0.f;
#pragma unroll
                for (int m = 0; m < 6; m++)
                    acc = fmaf(T[i * 6 + m], T[m * 6 + j], acc);
                tmp[i * 6 + j] = acc;
            }
#pragma unroll
        for (int i = 0; i < 36; i++) T[i] = tmp[i];
    }

    float* outp = d_R + idx * 36;
#pragma unroll
    for (int i = 0; i < 36; i++) outp[i] = T[i];
}

// ---------------------------------------------------------------------------
// Kernel 2: streaming apply with full smem staging.
// CTA = 128 threads = 2 b-values x 64 k blocks.
//   Phase 1: coalesced LDG.128 of gf slice (18KB) + R slices (18KB) -> smem
//   Phase 2: per-thread 6x6 matmul; LDS.128 at 144B stride is bank-conflict
//            free (8-thread phases, banks 4t+4q mod 32 all distinct).
//            P overwrites the thread's own G region (no sync needed).
//   Phase 3: coalesced STG.128 from smem.
// ---------------------------------------------------------------------------
__global__ void __launch_bounds__(128, 4) apply_kernel(
    const float* __restrict__ gf,
    const int* __restrict__ act,
    float* __restrict__ out) {
    __shared__ __align__(16) float sG[128 * 36];   // 18 KB, reused for output
    __shared__ __align__(16) float sR[128 * 36];   // 18 KB

    const int t = threadIdx.x;
    const size_t base_f4 = (size_t)blockIdx.x * 1152;   // 128 blocks * 9 f4

    const float4* g4 = reinterpret_cast<const float4*>(gf);
    float4* sG4 = reinterpret_cast<float4*>(sG);
    float4* sR4 = reinterpret_cast<float4*>(sR);

    // Phase 1a: stage gf (fully coalesced)
#pragma unroll
    for (int i = 0; i < 9; i++)
        sG4[i * 128 + t] = g4[base_f4 + i * 128 + t];

    // Phase 1b: stage R for the two b's of this CTA (coalesced within halves)
    const unsigned b0 = blockIdx.x * 2u;
    const int a0 = __ldg(act + b0);
    const int a1 = __ldg(act + b0 + 1);
    const float4* R4 = reinterpret_cast<const float4*>(d_R);
    const unsigned ra0 = (unsigned)a0 * 576u;   // f4 offset of R[a0][0]
    const unsigned ra1 = (unsigned)a1 * 576u;
#pragma unroll
    for (int i = 0; i < 9; i++) {
        unsigned j = i * 128 + t;               // 0..1151
        unsigned src = (j < 576u) ? (ra0 + j) : (ra1 + (j - 576u));
        sR4[j] = R4[src];
    }
    __syncthreads();

    // Phase 2: 6x6 matmul. Thread t owns block #t of the CTA.
    float G[36];
    const float4* myG = sG4 + t * 9;
#pragma unroll
    for (int q = 0; q < 9; q++) {
        float4 v = myG[q];
        G[4 * q + 0] = v.x; G[4 * q + 1] = v.y;
        G[4 * q + 2] = v.z; G[4 * q + 3] = v.w;
    }

    const float4* myR = sR4 + t * 9;
    float4* myO = sG4 + t * 9;                  // overwrite own G region
#pragma unroll
    for (int rp = 0; rp < 3; rp++) {
        float r[12];
#pragma unroll
        for (int q = 0; q < 3; q++) {
            float4 v = myR[rp * 3 + q];
            r[4 * q + 0] = v.x; r[4 * q + 1] = v.y;
            r[4 * q + 2] = v.z; r[4 * q + 3] = v.w;
        }
        float p[12];
#pragma unroll
        for (int l = 0; l < 6; l++) {
            float acc0 = 0.f, acc1 = 0.f;
#pragma unroll
            for (int j = 0; j < 6; j++) {
                acc0 = fmaf(r[j],     G[j * 6 + l], acc0);
                acc1 = fmaf(r[6 + j], G[j * 6 + l], acc1);
            }
            p[l] = acc0; p[6 + l] = acc1;
        }
#pragma unroll
        for (int q = 0; q < 3; q++) {
            float4 v;
            v.x = p[4 * q + 0]; v.y = p[4 * q + 1];
            v.z = p[4 * q + 2]; v.w = p[4 * q + 3];
            myO[rp * 3 + q] = v;
        }
    }
    __syncthreads();

    // Phase 3: coalesced store
    float4* o4 = reinterpret_cast<float4*>(out);
#pragma unroll
    for (int i = 0; i < 9; i++)
        o4[base_f4 + i * 128 + t] = sG4[i * 128 + t];
}

// ---------------------------------------------------------------------------
// Inputs (metadata order): group_feats f32 [B,K*36], act i32 [B],
// act_params f32 [16,K], lie_alg_basis f32 [K,6,6]. Output f32 [B,K*36].
// ---------------------------------------------------------------------------
extern "C" void kernel_launch(void* const* d_in, const int* in_sizes, int n_in,
                              void* d_out, int out_size) {
    const float* gf         = (const float*)d_in[0];
    const int*   act        = (const int*)d_in[1];
    const float* act_params = (const float*)d_in[2];
    const float* basis      = (const float*)d_in[3];
    float* out = (float*)d_out;

    expm_kernel<<<32, 32>>>(act_params, basis);
    apply_kernel<<<BB / 2, 128>>>(gf, act, out);
}

// round 5
// speedup vs baseline: 1.6012x; 1.3780x over previous
#include <cuda_runtime.h>
#include <cstdint>

#define BB 16384
#define KK 64
#define NA 16

// Precomputed rotation table: R[action][k][6][6]  (144 KB), 128B-aligned.
__device__ __align__(128) float d_R[NA * KK * 36];

static __device__ __forceinline__ uint32_t smem_u32(const void* p) {
    uint32_t a;
    asm("{ .reg .u64 t; cvta.to.shared.u64 t, %1; cvt.u32.u64 %0, t; }"
        : "=r"(a) : "l"(p));
    return a;
}

// ---------------------------------------------------------------------------
// Kernel 1: the 1024 distinct 6x6 expm's. One thread per (action,k).
// ---------------------------------------------------------------------------
__global__ void expm_kernel(const float* __restrict__ act_params,
                            const float* __restrict__ basis) {
    int idx = blockIdx.x * blockDim.x + threadIdx.x;
    if (idx >= NA * KK) return;
    int action = idx >> 6;
    int k = idx & 63;

    float a = act_params[action * KK + k];
    const float* L = basis + k * 36;

    float A[36];
#pragma unroll
    for (int i = 0; i < 6; i++)
#pragma unroll
        for (int j = 0; j < 6; j++)
            A[i * 6 + j] = a * (L[i * 6 + j] - L[j * 6 + i]);

    float nrm = 0.f;
#pragma unroll
    for (int i = 0; i < 6; i++) {
        float rs = 0.f;
#pragma unroll
        for (int j = 0; j < 6; j++) rs += fabsf(A[i * 6 + j]);
        nrm = fmaxf(nrm, rs);
    }

    int s = 0;
    while (nrm > 0.5f && s < 40) { nrm *= 0.5f; s++; }
    float sc = ldexpf(1.0f, -s);
#pragma unroll
    for (int i = 0; i < 36; i++) A[i] *= sc;

    // Taylor (order 10) via Horner: T = I; for p=10..1: T = I + (A*T)/p
    float T[36];
#pragma unroll
    for (int i = 0; i < 36; i++) T[i] = 0.f;
#pragma unroll
    for (int i = 0; i < 6; i++) T[i * 6 + i] = 1.f;

    for (int p = 10; p >= 1; --p) {
        float tmp[36];
        float inv = 1.0f / (float)p;
#pragma unroll
        for (int i = 0; i < 6; i++)
#pragma unroll
            for (int j = 0; j < 6; j++) {
                float acc = 0.f;
#pragma unroll
                for (int m = 0; m < 6; m++)
                    acc = fmaf(A[i * 6 + m], T[m * 6 + j], acc);
                tmp[i * 6 + j] = acc * inv + ((i == j) ? 1.f : 0.f);
            }
#pragma unroll
        for (int i = 0; i < 36; i++) T[i] = tmp[i];
    }

    for (int q = 0; q < s; q++) {
        float tmp[36];
#pragma unroll
        for (int i = 0; i < 6; i++)
#pragma unroll
            for (int j = 0; j < 6; j++) {
                float acc = 0.f;
#pragma unroll
                for (int m = 0; m < 6; m++)
                    acc = fmaf(T[i * 6 + m], T[m * 6 + j], acc);
                tmp[i * 6 + j] = acc;
            }
#pragma unroll
        for (int i = 0; i < 36; i++) T[i] = tmp[i];
    }

    float* outp = d_R + idx * 36;
#pragma unroll
    for (int i = 0; i < 36; i++) outp[i] = T[i];
}

// ---------------------------------------------------------------------------
// Kernel 2: apply with TMA bulk-async staging (UBLKCP).
// CTA = 128 threads = 2 b-values x 64 k blocks.
//   In : cp.async.bulk gf slice (18KB) + R[a0],R[a1] (9KB each) -> smem,
//        single mbarrier with expect_tx(36864).
//   Mid: per-thread 6x6 matmul via conflict-free LDS.128 / STS.128.
//   Out: cp.async.bulk shared->global (18KB), bulk_group.
// LSU wavefront work per CTA drops from ~1300 to ~432 cycles.
// ---------------------------------------------------------------------------
#define GF_BYTES 18432u          // 128 blocks * 36 floats * 4
#define R_BYTES  9216u           // 64 blocks * 36 floats * 4

__global__ void __launch_bounds__(128, 6) apply_kernel(
    const float* __restrict__ gf,
    const int* __restrict__ act,
    float* __restrict__ out) {
    __shared__ __align__(128) float sG[128 * 36];   // 18 KB, reused for output
    __shared__ __align__(128) float sR[128 * 36];   // 18 KB
    __shared__ __align__(8) unsigned long long mbar;

    const int t = threadIdx.x;
    const uint32_t sG_a = smem_u32(sG);
    const uint32_t sR_a = smem_u32(sR);
    const uint32_t bar_a = smem_u32(&mbar);

    if (t == 0)
        asm volatile("mbarrier.init.shared.b64 [%0], 1;" :: "r"(bar_a) : "memory");
    __syncthreads();

    if (t == 0) {
        asm volatile("mbarrier.arrive.expect_tx.shared.b64 _, [%0], %1;"
                     :: "r"(bar_a), "r"(GF_BYTES + 2u * R_BYTES) : "memory");
        // gf slice first: flows while the act[] loads resolve
        const char* gsrc = reinterpret_cast<const char*>(gf) +
                           (size_t)blockIdx.x * GF_BYTES;
        asm volatile(
            "cp.async.bulk.shared::cta.global.mbarrier::complete_tx::bytes "
            "[%0], [%1], %2, [%3];"
            :: "r"(sG_a), "l"(gsrc), "r"(GF_BYTES), "r"(bar_a) : "memory");

        const unsigned b0 = blockIdx.x * 2u;
        int a0 = __ldg(act + b0);
        int a1 = __ldg(act + b0 + 1);
        const char* rbase = reinterpret_cast<const char*>(d_R);
        asm volatile(
            "cp.async.bulk.shared::cta.global.mbarrier::complete_tx::bytes "
            "[%0], [%1], %2, [%3];"
            :: "r"(sR_a), "l"(rbase + (size_t)a0 * R_BYTES), "r"(R_BYTES),
               "r"(bar_a) : "memory");
        asm volatile(
            "cp.async.bulk.shared::cta.global.mbarrier::complete_tx::bytes "
            "[%0], [%1], %2, [%3];"
            :: "r"(sR_a + R_BYTES), "l"(rbase + (size_t)a1 * R_BYTES),
               "r"(R_BYTES), "r"(bar_a) : "memory");
    }

    // Wait for all 36864 bytes (parity 0)
    {
        uint32_t done;
        asm volatile(
            "{\n\t.reg .pred p;\n\t"
            "mbarrier.try_wait.parity.acquire.cta.shared::cta.b64 p, [%1], 0;\n\t"
            "selp.b32 %0, 1, 0, p;\n\t}"
            : "=r"(done) : "r"(bar_a) : "memory");
        if (!done) {
            asm volatile(
                "{\n\t.reg .pred P1;\n\t"
                "WL_%=:\n\t"
                "mbarrier.try_wait.parity.acquire.cta.shared::cta.b64 P1, [%0], 0, 0x989680;\n\t"
                "@P1 bra.uni WD_%=;\n\t"
                "bra.uni WL_%=;\n\t"
                "WD_%=:\n\t}"
                :: "r"(bar_a) : "memory");
        }
    }

    // Compute: thread t owns block #t. Conflict-free LDS.128 at 144B stride.
    float4* sG4 = reinterpret_cast<float4*>(sG);
    float4* sR4 = reinterpret_cast<float4*>(sR);

    float G[36];
    const float4* myG = sG4 + t * 9;
#pragma unroll
    for (int q = 0; q < 9; q++) {
        float4 v = myG[q];
        G[4 * q + 0] = v.x; G[4 * q + 1] = v.y;
        G[4 * q + 2] = v.z; G[4 * q + 3] = v.w;
    }

    const float4* myR = sR4 + t * 9;
    float4* myO = sG4 + t * 9;                  // overwrite own G region
#pragma unroll
    for (int rp = 0; rp < 3; rp++) {
        float r[12];
#pragma unroll
        for (int q = 0; q < 3; q++) {
            float4 v = myR[rp * 3 + q];
            r[4 * q + 0] = v.x; r[4 * q + 1] = v.y;
            r[4 * q + 2] = v.z; r[4 * q + 3] = v.w;
        }
        float p[12];
#pragma unroll
        for (int l = 0; l < 6; l++) {
            float acc0 = 0.f, acc1 = 0.f;
#pragma unroll
            for (int j = 0; j < 6; j++) {
                acc0 = fmaf(r[j],     G[j * 6 + l], acc0);
                acc1 = fmaf(r[6 + j], G[j * 6 + l], acc1);
            }
            p[l] = acc0; p[6 + l] = acc1;
        }
#pragma unroll
        for (int q = 0; q < 3; q++) {
            float4 v;
            v.x = p[4 * q + 0]; v.y = p[4 * q + 1];
            v.z = p[4 * q + 2]; v.w = p[4 * q + 3];
            myO[rp * 3 + q] = v;
        }
    }

    // Make generic-proxy STS visible to the async proxy, then bulk store.
    asm volatile("fence.proxy.async.shared::cta;" ::: "memory");
    __syncthreads();

    if (t == 0) {
        char* gdst = reinterpret_cast<char*>(out) + (size_t)blockIdx.x * GF_BYTES;
        asm volatile(
            "cp.async.bulk.global.shared::cta.bulk_group [%0], [%1], %2;"
            :: "l"(gdst), "r"(sG_a), "r"(GF_BYTES) : "memory");
        asm volatile("cp.async.bulk.commit_group;" ::: "memory");
        asm volatile("cp.async.bulk.wait_group 0;" ::: "memory");
    }
}

// ---------------------------------------------------------------------------
// Inputs (metadata order): group_feats f32 [B,K*36], act i32 [B],
// act_params f32 [16,K], lie_alg_basis f32 [K,6,6]. Output f32 [B,K*36].
// ---------------------------------------------------------------------------
extern "C" void kernel_launch(void* const* d_in, const int* in_sizes, int n_in,
                              void* d_out, int out_size) {
    const float* gf         = (const float*)d_in[0];
    const int*   act        = (const int*)d_in[1];
    const float* act_params = (const float*)d_in[2];
    const float* basis      = (const float*)d_in[3];
    float* out = (float*)d_out;

    expm_kernel<<<32, 32>>>(act_params, basis);
    apply_kernel<<<BB / 2, 128>>>(gf, act, out);
}